// round 1
// baseline (speedup 1.0000x reference)
#include <cuda_runtime.h>

#define NN 50000
#define NE 800000
#define HID 64

// ---------------- device scratch (no allocations allowed) ----------------
__device__ float g_x[NN * HID];        // current node features
__device__ float g_sc[NN * HID];       // skip connection (embedding output)
__device__ float g_AB[NN * 2 * HID];   // per-node A (cols 0..63) and B (cols 64..127)
__device__ float g_t[NN * HID];        // x + m_i (input to update GEMM)
__device__ int   g_rowptr[NN + 1];
__device__ int   g_cur[NN];
__device__ int   g_csrdst[NE];
__device__ int   g_is64;

__device__ __forceinline__ float fsilu(float v) {
    return __fdividef(v, 1.0f + __expf(-v));
}

// ---------------- edge index dtype detection (int64 vs int32) ----------------
__global__ void k_detect(const int* __restrict__ ei32) {
    if (threadIdx.x == 0 && blockIdx.x == 0) {
        int all0 = 1;
        for (int i = 0; i < 64; i++) {
            if (ei32[2 * i + 1] != 0) { all0 = 0; break; }
        }
        g_is64 = all0;
    }
}

__device__ __forceinline__ void load_edge(const void* ei, int i, int& s, int& d) {
    if (g_is64) {
        const long long* p = (const long long*)ei;
        s = (int)p[i];
        d = (int)p[NE + i];
    } else {
        const int* p = (const int*)ei;
        s = p[i];
        d = p[NE + i];
    }
}

// ---------------- CSR build ----------------
__global__ void k_zero() {
    int i = blockIdx.x * blockDim.x + threadIdx.x;
    if (i < NN) g_cur[i] = 0;
}

__global__ void k_hist(const void* __restrict__ ei) {
    int i = blockIdx.x * blockDim.x + threadIdx.x;
    if (i >= NE) return;
    int s, d;
    load_edge(ei, i, s, d);
    atomicAdd(&g_cur[s], 1);
}

__global__ void k_scan() {
    __shared__ int s[1024];
    int tid = threadIdx.x;
    int running = 0;
    for (int base = 0; base < NN; base += 1024) {
        int i = base + tid;
        int v = (i < NN) ? g_cur[i] : 0;
        s[tid] = v;
        __syncthreads();
        for (int off = 1; off < 1024; off <<= 1) {
            int t = (tid >= off) ? s[tid - off] : 0;
            __syncthreads();
            s[tid] += t;
            __syncthreads();
        }
        if (i < NN) {
            int excl = running + s[tid] - v;
            g_rowptr[i] = excl;
            g_cur[i] = excl;
        }
        running += s[1023];
        __syncthreads();
    }
    if (tid == 0) g_rowptr[NN] = running;
}

__global__ void k_scatter(const void* __restrict__ ei) {
    int i = blockIdx.x * blockDim.x + threadIdx.x;
    if (i >= NE) return;
    int s, d;
    load_edge(ei, i, s, d);
    int p = atomicAdd(&g_cur[s], 1);
    g_csrdst[p] = d;
}

// ---------------- embedding: x = silu(cat[oh, pos] @ W + b) ----------------
__global__ __launch_bounds__(256) void k_emb(
    const float* __restrict__ oh, const float* __restrict__ pos,
    const float* __restrict__ W, const float* __restrict__ b)
{
    __shared__ float a_s[32][68];   // [k][m]
    __shared__ float w_s[32][64];   // [k][n]
    int m0 = blockIdx.x * 64;
    int tx = threadIdx.x & 15, ty = threadIdx.x >> 4;
    float acc[4][4];
    #pragma unroll
    for (int i = 0; i < 4; i++)
        #pragma unroll
        for (int j = 0; j < 4; j++) acc[i][j] = 0.f;

    for (int k0 = 0; k0 < 121; k0 += 32) {
        __syncthreads();
        for (int idx = threadIdx.x; idx < 2048; idx += 256) {
            int m = idx & 63, k = idx >> 6;
            int gm = m0 + m, gk = k0 + k;
            float v = 0.f;
            if (gm < NN) {
                if (gk < 118)       v = oh[gm * 118 + gk];
                else if (gk < 121)  v = pos[gm * 3 + gk - 118];
            }
            a_s[k][m] = v;
        }
        for (int idx = threadIdx.x; idx < 2048; idx += 256) {
            int n = idx & 63, k = idx >> 6;
            int gk = k0 + k;
            w_s[k][n] = (gk < 121) ? W[gk * 64 + n] : 0.f;
        }
        __syncthreads();
        #pragma unroll
        for (int k = 0; k < 32; k++) {
            float4 a4 = *(const float4*)&a_s[k][ty * 4];
            float4 w4 = *(const float4*)&w_s[k][tx * 4];
            float av[4] = {a4.x, a4.y, a4.z, a4.w};
            float wv[4] = {w4.x, w4.y, w4.z, w4.w};
            #pragma unroll
            for (int i = 0; i < 4; i++)
                #pragma unroll
                for (int j = 0; j < 4; j++)
                    acc[i][j] += av[i] * wv[j];
        }
    }
    #pragma unroll
    for (int i = 0; i < 4; i++) {
        int m = m0 + ty * 4 + i;
        if (m >= NN) continue;
        #pragma unroll
        for (int j = 0; j < 4; j++) {
            int n = tx * 4 + j;
            float v = fsilu(acc[i][j] + b[n]);
            g_x[m * 64 + n] = v;
            g_sc[m * 64 + n] = v;
        }
    }
}

// ---------------- layer GEMMs ----------------
// ABM=true : g_AB = g_x @ [W_top | W_bot]  (W is interact_W[l], shape 128x64)
// ABM=false: g_x += silu(g_t @ W + bias)   (W is update_W[l],   shape 64x64)
template <int NC, bool ABM>
__global__ __launch_bounds__(256) void k_gemm(
    const float* __restrict__ Wsrc, const float* __restrict__ bias)
{
    __shared__ float a_s[32][68];
    __shared__ float w_s[32][NC];
    constexpr int TN = NC / 16;
    const float* in = ABM ? g_x : g_t;
    int m0 = blockIdx.x * 64;
    int tx = threadIdx.x & 15, ty = threadIdx.x >> 4;
    float acc[4][TN];
    #pragma unroll
    for (int i = 0; i < 4; i++)
        #pragma unroll
        for (int j = 0; j < TN; j++) acc[i][j] = 0.f;

    for (int k0 = 0; k0 < 64; k0 += 32) {
        __syncthreads();
        for (int idx = threadIdx.x; idx < 2048; idx += 256) {
            int m = idx & 63, k = idx >> 6;
            int gm = m0 + m;
            a_s[k][m] = (gm < NN) ? in[gm * 64 + k0 + k] : 0.f;
        }
        for (int idx = threadIdx.x; idx < 32 * NC; idx += 256) {
            int n = idx % NC, k = idx / NC;
            float v;
            if (ABM) {
                int col = n & 63;
                int row = (n < 64) ? (k0 + k) : (64 + k0 + k);
                v = Wsrc[row * 64 + col];
            } else {
                v = Wsrc[(k0 + k) * 64 + n];
            }
            w_s[k][n] = v;
        }
        __syncthreads();
        #pragma unroll
        for (int k = 0; k < 32; k++) {
            float4 a4 = *(const float4*)&a_s[k][ty * 4];
            float av[4] = {a4.x, a4.y, a4.z, a4.w};
            float wv[TN];
            #pragma unroll
            for (int g = 0; g < TN; g += 4) {
                float4 w4 = *(const float4*)&w_s[k][tx * TN + g];
                wv[g] = w4.x; wv[g + 1] = w4.y; wv[g + 2] = w4.z; wv[g + 3] = w4.w;
            }
            #pragma unroll
            for (int i = 0; i < 4; i++)
                #pragma unroll
                for (int j = 0; j < TN; j++)
                    acc[i][j] += av[i] * wv[j];
        }
    }
    #pragma unroll
    for (int i = 0; i < 4; i++) {
        int m = m0 + ty * 4 + i;
        if (m >= NN) continue;
        #pragma unroll
        for (int j = 0; j < TN; j++) {
            int n = tx * TN + j;
            if (ABM) {
                g_AB[m * 128 + n] = acc[i][j];
            } else {
                float u = fsilu(acc[i][j] + bias[n]);
                g_x[m * 64 + n] += u;
            }
        }
    }
}

// ---------------- edge aggregation: t = x + 0.25 * sum_e silu(A[src]+B[dst]+b) ----------------
__global__ __launch_bounds__(256) void k_edge(const float* __restrict__ bias) {
    int gt = blockIdx.x * blockDim.x + threadIdx.x;
    int n = gt >> 5;
    int lane = gt & 31;
    if (n >= NN) return;
    float b0 = bias[lane], b1 = bias[lane + 32];
    const float* Ar = g_AB + n * 128;
    float a0 = Ar[lane], a1 = Ar[lane + 32];
    float acc0 = 0.f, acc1 = 0.f;
    int e0 = g_rowptr[n], e1 = g_rowptr[n + 1];
    for (int e = e0; e < e1; e++) {
        int d = g_csrdst[e];
        const float* Br = g_AB + d * 128 + 64;
        acc0 += fsilu(a0 + Br[lane]      + b0);
        acc1 += fsilu(a1 + Br[lane + 32] + b1);
    }
    g_t[n * 64 + lane]      = g_x[n * 64 + lane]      + 0.25f * acc0;
    g_t[n * 64 + lane + 32] = g_x[n * 64 + lane + 32] + 0.25f * acc1;
}

// ---------------- output: out = (sc + x) @ Wo + bo ----------------
__global__ __launch_bounds__(256) void k_out(
    const float* __restrict__ Wo, const float* __restrict__ bo, float* __restrict__ out)
{
    int gt = blockIdx.x * blockDim.x + threadIdx.x;
    int n = gt >> 5;
    int lane = gt & 31;
    if (n >= NN) return;
    float v0 = g_sc[n * 64 + lane]      + g_x[n * 64 + lane];
    float v1 = g_sc[n * 64 + lane + 32] + g_x[n * 64 + lane + 32];
    float p0 = v0 * Wo[lane * 3 + 0] + v1 * Wo[(lane + 32) * 3 + 0];
    float p1 = v0 * Wo[lane * 3 + 1] + v1 * Wo[(lane + 32) * 3 + 1];
    float p2 = v0 * Wo[lane * 3 + 2] + v1 * Wo[(lane + 32) * 3 + 2];
    #pragma unroll
    for (int off = 16; off; off >>= 1) {
        p0 += __shfl_down_sync(0xffffffffu, p0, off);
        p1 += __shfl_down_sync(0xffffffffu, p1, off);
        p2 += __shfl_down_sync(0xffffffffu, p2, off);
    }
    if (lane == 0) {
        out[n * 3 + 0] = p0 + bo[0];
        out[n * 3 + 1] = p1 + bo[1];
        out[n * 3 + 2] = p2 + bo[2];
    }
}

// ---------------- launch ----------------
extern "C" void kernel_launch(void* const* d_in, const int* in_sizes, int n_in,
                              void* d_out, int out_size)
{
    const float* oh   = (const float*)d_in[0];
    const float* pos  = (const float*)d_in[1];
    const void*  ei   = d_in[2];
    const float* embW = (const float*)d_in[3];
    const float* embB = (const float*)d_in[4];
    const float* iW   = (const float*)d_in[5];   // [4][128][64]
    const float* iB   = (const float*)d_in[6];   // [4][64]
    const float* uW   = (const float*)d_in[7];   // [4][64][64]
    const float* uB   = (const float*)d_in[8];   // [4][64]
    const float* oW   = (const float*)d_in[9];   // [64][3]
    const float* oB   = (const float*)d_in[10];  // [3]
    float* out = (float*)d_out;

    k_detect<<<1, 32>>>((const int*)ei);

    // CSR build (amortized over 4 layers)
    k_zero<<<(NN + 255) / 256, 256>>>();
    k_hist<<<(NE + 255) / 256, 256>>>(ei);
    k_scan<<<1, 1024>>>();
    k_scatter<<<(NE + 255) / 256, 256>>>(ei);

    k_emb<<<(NN + 63) / 64, 256>>>(oh, pos, embW, embB);

    for (int l = 0; l < 4; l++) {
        k_gemm<128, true><<<(NN + 63) / 64, 256>>>(iW + l * 128 * 64, nullptr);
        k_edge<<<(NN * 32) / 256, 256>>>(iB + l * 64);
        k_gemm<64, false><<<(NN + 63) / 64, 256>>>(uW + l * 64 * 64, uB + l * 64);
    }

    k_out<<<(NN * 32) / 256, 256>>>(oW, oB, out);
}

// round 2
// speedup vs baseline: 1.1099x; 1.1099x over previous
#include <cuda_runtime.h>

#define NN 50000
#define NE 800000
#define HID 64
#define NB_SCAN 196   // ceil(NN/256)

// ---------------- device scratch ----------------
__device__ float g_x[NN * HID];
__device__ float g_sc[NN * HID];
__device__ float g_A[NN * HID];     // x @ W_top
__device__ float g_B[NN * HID];     // x @ W_bot
__device__ float g_t[NN * HID];     // x + 0.25*m_i
__device__ int   g_rowptr[NN + 1];
__device__ int   g_cur[NN];
__device__ int   g_csrdst[NE];
__device__ int   g_bsum[256];
__device__ int   g_is64;

__device__ __forceinline__ float fsilu(float v) {
    return __fdividef(v, 1.0f + __expf(-v));
}

__device__ __forceinline__ unsigned f2tf32(float v) {
    unsigned r;
    asm("cvt.rna.tf32.f32 %0, %1;" : "=r"(r) : "f"(v));
    return r;
}

__device__ __forceinline__ void mma_tf32(float c[4], const unsigned a[4],
                                         unsigned b0, unsigned b1) {
    asm volatile(
        "mma.sync.aligned.m16n8k8.row.col.f32.tf32.tf32.f32 "
        "{%0,%1,%2,%3},{%4,%5,%6,%7},{%8,%9},{%0,%1,%2,%3};\n"
        : "+f"(c[0]), "+f"(c[1]), "+f"(c[2]), "+f"(c[3])
        : "r"(a[0]), "r"(a[1]), "r"(a[2]), "r"(a[3]), "r"(b0), "r"(b1));
}

// ---------------- edge index dtype detection ----------------
__global__ void k_detect(const int* __restrict__ ei32) {
    if (threadIdx.x == 0 && blockIdx.x == 0) {
        int all0 = 1;
        for (int i = 0; i < 64; i++)
            if (ei32[2 * i + 1] != 0) { all0 = 0; break; }
        g_is64 = all0;
    }
}

__device__ __forceinline__ void load_edge(const void* ei, int i, int& s, int& d) {
    if (g_is64) {
        const long long* p = (const long long*)ei;
        s = (int)p[i];
        d = (int)p[NE + i];
    } else {
        const int* p = (const int*)ei;
        s = p[i];
        d = p[NE + i];
    }
}

// ---------------- CSR build ----------------
__global__ void k_zero() {
    int i = blockIdx.x * blockDim.x + threadIdx.x;
    if (i < NN) g_cur[i] = 0;
}

__global__ void k_hist(const void* __restrict__ ei) {
    int i = blockIdx.x * blockDim.x + threadIdx.x;
    if (i >= NE) return;
    int s, d;
    load_edge(ei, i, s, d);
    atomicAdd(&g_cur[s], 1);
}

// two-level scan: per-block scan + partials
__global__ void k_scan1() {
    __shared__ int wsum[8];
    int tid = threadIdx.x;
    int i = blockIdx.x * 256 + tid;
    int lane = tid & 31, warp = tid >> 5;
    int v = (i < NN) ? g_cur[i] : 0;
    int s = v;
    #pragma unroll
    for (int off = 1; off < 32; off <<= 1) {
        int t = __shfl_up_sync(0xffffffffu, s, off);
        if (lane >= off) s += t;
    }
    if (lane == 31) wsum[warp] = s;
    __syncthreads();
    if (tid == 0) {
        int run = 0;
        #pragma unroll
        for (int j = 0; j < 8; j++) { int t = wsum[j]; wsum[j] = run; run += t; }
    }
    __syncthreads();
    int excl = s - v + wsum[warp];
    if (i < NN) g_rowptr[i] = excl;
    if (tid == 255) g_bsum[blockIdx.x] = excl + v;
}

__global__ void k_scan2() {
    __shared__ int wsum[8];
    int tid = threadIdx.x;
    int lane = tid & 31, warp = tid >> 5;
    int v = (tid < NB_SCAN) ? g_bsum[tid] : 0;
    int s = v;
    #pragma unroll
    for (int off = 1; off < 32; off <<= 1) {
        int t = __shfl_up_sync(0xffffffffu, s, off);
        if (lane >= off) s += t;
    }
    if (lane == 31) wsum[warp] = s;
    __syncthreads();
    if (tid == 0) {
        int run = 0;
        #pragma unroll
        for (int j = 0; j < 8; j++) { int t = wsum[j]; wsum[j] = run; run += t; }
    }
    __syncthreads();
    int excl = s - v + wsum[warp];
    if (tid < NB_SCAN) g_bsum[tid] = excl;
    if (tid == 255) g_rowptr[NN] = excl + v;
}

__global__ void k_scan3() {
    int i = blockIdx.x * 256 + threadIdx.x;
    if (i < NN) {
        int r = g_rowptr[i] + g_bsum[blockIdx.x];
        g_rowptr[i] = r;
        g_cur[i] = r;
    }
}

__global__ void k_scatter(const void* __restrict__ ei) {
    int i = blockIdx.x * blockDim.x + threadIdx.x;
    if (i >= NE) return;
    int s, d;
    load_edge(ei, i, s, d);
    int p = atomicAdd(&g_cur[s], 1);
    g_csrdst[p] = d;
}

// ---------------- embedding (fp32 SIMT) ----------------
__global__ __launch_bounds__(256) void k_emb(
    const float* __restrict__ oh, const float* __restrict__ pos,
    const float* __restrict__ W, const float* __restrict__ b)
{
    __shared__ float a_s[32][68];
    __shared__ float w_s[32][64];
    int m0 = blockIdx.x * 64;
    int tx = threadIdx.x & 15, ty = threadIdx.x >> 4;
    float acc[4][4];
    #pragma unroll
    for (int i = 0; i < 4; i++)
        #pragma unroll
        for (int j = 0; j < 4; j++) acc[i][j] = 0.f;

    for (int k0 = 0; k0 < 121; k0 += 32) {
        __syncthreads();
        for (int idx = threadIdx.x; idx < 2048; idx += 256) {
            int m = idx & 63, k = idx >> 6;
            int gm = m0 + m, gk = k0 + k;
            float v = 0.f;
            if (gm < NN) {
                if (gk < 118)      v = oh[gm * 118 + gk];
                else if (gk < 121) v = pos[gm * 3 + gk - 118];
            }
            a_s[k][m] = v;
        }
        for (int idx = threadIdx.x; idx < 2048; idx += 256) {
            int n = idx & 63, k = idx >> 6;
            int gk = k0 + k;
            w_s[k][n] = (gk < 121) ? W[gk * 64 + n] : 0.f;
        }
        __syncthreads();
        #pragma unroll
        for (int k = 0; k < 32; k++) {
            float4 a4 = *(const float4*)&a_s[k][ty * 4];
            float4 w4 = *(const float4*)&w_s[k][tx * 4];
            float av[4] = {a4.x, a4.y, a4.z, a4.w};
            float wv[4] = {w4.x, w4.y, w4.z, w4.w};
            #pragma unroll
            for (int i = 0; i < 4; i++)
                #pragma unroll
                for (int j = 0; j < 4; j++)
                    acc[i][j] += av[i] * wv[j];
        }
    }
    #pragma unroll
    for (int i = 0; i < 4; i++) {
        int m = m0 + ty * 4 + i;
        if (m >= NN) continue;
        #pragma unroll
        for (int j = 0; j < 4; j++) {
            int n = tx * 4 + j;
            float v = fsilu(acc[i][j] + b[n]);
            g_x[m * 64 + n] = v;
            g_sc[m * 64 + n] = v;
        }
    }
}

// ---------------- tf32 split GEMM: out = in(50000x64) @ W(64x64) ----------------
// STORE_RAW: outp[m*64+n] = acc          (interact A/B precompute)
// else     : g_x[m*64+n] += silu(acc+b)  (update layer)
template <bool STORE_RAW>
__global__ __launch_bounds__(256) void k_gemm_t(
    const float* __restrict__ in, const float* __restrict__ W,
    float* __restrict__ outp, const float* __restrict__ bias)
{
    __shared__ unsigned w_hi[64][65];
    __shared__ unsigned w_lo[64][65];
    int tid = threadIdx.x;
    int lane = tid & 31, warp = tid >> 5;

    // stage W hi/lo (coalesced)
    for (int idx = tid; idx < 4096; idx += 256) {
        int k = idx >> 6, n = idx & 63;
        float v = W[idx];
        unsigned hi = f2tf32(v);
        unsigned lo = f2tf32(v - __uint_as_float(hi));
        w_hi[k][n] = hi;
        w_lo[k][n] = lo;
    }
    __syncthreads();

    int m0 = blockIdx.x * 128 + warp * 16;

    // load A fragments (8 k-tiles), hi/lo
    unsigned a_hi[8][4], a_lo[8][4];
    int r0 = m0 + (lane >> 2);
    int c0 = lane & 3;
    #pragma unroll
    for (int kt = 0; kt < 8; kt++) {
        #pragma unroll
        for (int e = 0; e < 4; e++) {
            int r = r0 + (e & 1) * 8;
            int c = kt * 8 + c0 + (e >> 1) * 4;
            float v = in[min(r, NN - 1) * 64 + c];
            unsigned hi = f2tf32(v);
            a_hi[kt][e] = hi;
            a_lo[kt][e] = f2tf32(v - __uint_as_float(hi));
        }
    }

    #pragma unroll
    for (int nt = 0; nt < 8; nt++) {
        float c4[4] = {0.f, 0.f, 0.f, 0.f};
        int bn = nt * 8 + (lane >> 2);
        #pragma unroll
        for (int kt = 0; kt < 8; kt++) {
            int bk = kt * 8 + (lane & 3);
            unsigned bh0 = w_hi[bk][bn];
            unsigned bh1 = w_hi[bk + 4][bn];
            unsigned bl0 = w_lo[bk][bn];
            unsigned bl1 = w_lo[bk + 4][bn];
            mma_tf32(c4, a_hi[kt], bh0, bh1);
            mma_tf32(c4, a_lo[kt], bh0, bh1);
            mma_tf32(c4, a_hi[kt], bl0, bl1);
        }
        // store: c0/c1 at (row, 2*(lane%4)), c2/c3 at (row+8, ...)
        int col = nt * 8 + 2 * (lane & 3);
        int rA = m0 + (lane >> 2);
        int rB = rA + 8;
        if (STORE_RAW) {
            if (rA < NN) *(float2*)&outp[rA * 64 + col] = make_float2(c4[0], c4[1]);
            if (rB < NN) *(float2*)&outp[rB * 64 + col] = make_float2(c4[2], c4[3]);
        } else {
            float b0 = bias[col], b1 = bias[col + 1];
            if (rA < NN) {
                g_x[rA * 64 + col]     += fsilu(c4[0] + b0);
                g_x[rA * 64 + col + 1] += fsilu(c4[1] + b1);
            }
            if (rB < NN) {
                g_x[rB * 64 + col]     += fsilu(c4[2] + b0);
                g_x[rB * 64 + col + 1] += fsilu(c4[3] + b1);
            }
        }
    }
}

// ---------------- edge aggregation ----------------
__global__ __launch_bounds__(256) void k_edge(const float* __restrict__ bias) {
    int gt = blockIdx.x * blockDim.x + threadIdx.x;
    int n = gt >> 5;
    int lane = gt & 31;
    if (n >= NN) return;
    float b0 = bias[lane], b1 = bias[lane + 32];
    float a0 = g_A[n * 64 + lane], a1 = g_A[n * 64 + lane + 32];
    float acc0 = 0.f, acc1 = 0.f;
    int e0 = g_rowptr[n], e1 = g_rowptr[n + 1];
    for (int e = e0; e < e1; e++) {
        int d = g_csrdst[e];
        acc0 += fsilu(a0 + g_B[d * 64 + lane]      + b0);
        acc1 += fsilu(a1 + g_B[d * 64 + lane + 32] + b1);
    }
    g_t[n * 64 + lane]      = g_x[n * 64 + lane]      + 0.25f * acc0;
    g_t[n * 64 + lane + 32] = g_x[n * 64 + lane + 32] + 0.25f * acc1;
}

// ---------------- output ----------------
__global__ __launch_bounds__(256) void k_out(
    const float* __restrict__ Wo, const float* __restrict__ bo, float* __restrict__ out)
{
    int gt = blockIdx.x * blockDim.x + threadIdx.x;
    int n = gt >> 5;
    int lane = gt & 31;
    if (n >= NN) return;
    float v0 = g_sc[n * 64 + lane]      + g_x[n * 64 + lane];
    float v1 = g_sc[n * 64 + lane + 32] + g_x[n * 64 + lane + 32];
    float p0 = v0 * Wo[lane * 3 + 0] + v1 * Wo[(lane + 32) * 3 + 0];
    float p1 = v0 * Wo[lane * 3 + 1] + v1 * Wo[(lane + 32) * 3 + 1];
    float p2 = v0 * Wo[lane * 3 + 2] + v1 * Wo[(lane + 32) * 3 + 2];
    #pragma unroll
    for (int off = 16; off; off >>= 1) {
        p0 += __shfl_down_sync(0xffffffffu, p0, off);
        p1 += __shfl_down_sync(0xffffffffu, p1, off);
        p2 += __shfl_down_sync(0xffffffffu, p2, off);
    }
    if (lane == 0) {
        out[n * 3 + 0] = p0 + bo[0];
        out[n * 3 + 1] = p1 + bo[1];
        out[n * 3 + 2] = p2 + bo[2];
    }
}

// ---------------- launch ----------------
extern "C" void kernel_launch(void* const* d_in, const int* in_sizes, int n_in,
                              void* d_out, int out_size)
{
    const float* oh   = (const float*)d_in[0];
    const float* pos  = (const float*)d_in[1];
    const void*  ei   = d_in[2];
    const float* embW = (const float*)d_in[3];
    const float* embB = (const float*)d_in[4];
    const float* iW   = (const float*)d_in[5];   // [4][128][64]
    const float* iB   = (const float*)d_in[6];   // [4][64]
    const float* uW   = (const float*)d_in[7];   // [4][64][64]
    const float* uB   = (const float*)d_in[8];   // [4][64]
    const float* oW   = (const float*)d_in[9];   // [64][3]
    const float* oB   = (const float*)d_in[10];  // [3]
    float* out = (float*)d_out;

    k_detect<<<1, 32>>>((const int*)ei);

    k_zero<<<(NN + 255) / 256, 256>>>();
    k_hist<<<(NE + 255) / 256, 256>>>(ei);
    k_scan1<<<NB_SCAN, 256>>>();
    k_scan2<<<1, 256>>>();
    k_scan3<<<NB_SCAN, 256>>>();
    k_scatter<<<(NE + 255) / 256, 256>>>(ei);

    k_emb<<<(NN + 63) / 64, 256>>>(oh, pos, embW, embB);

    int gb = (NN + 127) / 128;
    float* gA; cudaGetSymbolAddress((void**)&gA, g_A);
    float* gB; cudaGetSymbolAddress((void**)&gB, g_B);
    float* gX; cudaGetSymbolAddress((void**)&gX, g_x);
    float* gT; cudaGetSymbolAddress((void**)&gT, g_t);

    for (int l = 0; l < 4; l++) {
        k_gemm_t<true><<<gb, 256>>>(gX, iW + l * 8192,        gA, nullptr);
        k_gemm_t<true><<<gb, 256>>>(gX, iW + l * 8192 + 4096, gB, nullptr);
        k_edge<<<(NN * 32) / 256, 256>>>(iB + l * 64);
        k_gemm_t<false><<<gb, 256>>>(gT, uW + l * 4096, nullptr, uB + l * 64);
    }

    k_out<<<(NN * 32) / 256, 256>>>(oW, oB, out);
}

// round 3
// speedup vs baseline: 1.8093x; 1.6301x over previous
#include <cuda_runtime.h>

#define NN 50000
#define NE 800000
#define HID 64
#define NB_SCAN 196   // ceil(NN/256)

// ---------------- device scratch ----------------
__device__ float g_x[NN * HID];
__device__ float g_sc[NN * HID];
__device__ float g_A[NN * HID];
__device__ float g_B[NN * HID];
__device__ float g_t[NN * HID];
__device__ int   g_rowptr[NN + 1];
__device__ int   g_cur[NN];
__device__ int   g_csrdst[NE];
__device__ int   g_bsum[256];
__device__ int   g_is64;

__device__ __forceinline__ float fsilu(float v) {
    return __fdividef(v, 1.0f + __expf(-v));
}

__device__ __forceinline__ unsigned f2tf32(float v) {
    unsigned r;
    asm("cvt.rna.tf32.f32 %0, %1;" : "=r"(r) : "f"(v));
    return r;
}

__device__ __forceinline__ void mma_tf32(float c[4], const unsigned a[4],
                                         unsigned b0, unsigned b1) {
    asm volatile(
        "mma.sync.aligned.m16n8k8.row.col.f32.tf32.tf32.f32 "
        "{%0,%1,%2,%3},{%4,%5,%6,%7},{%8,%9},{%0,%1,%2,%3};\n"
        : "+f"(c[0]), "+f"(c[1]), "+f"(c[2]), "+f"(c[3])
        : "r"(a[0]), "r"(a[1]), "r"(a[2]), "r"(a[3]), "r"(b0), "r"(b1));
}

// split-tf32 helper: 3 mmas ≈ fp32 product
__device__ __forceinline__ void mma3(float c[4], const unsigned ah[4], const unsigned al[4],
                                     unsigned bh0, unsigned bh1, unsigned bl0, unsigned bl1) {
    mma_tf32(c, ah, bh0, bh1);
    mma_tf32(c, al, bh0, bh1);
    mma_tf32(c, ah, bl0, bl1);
}

// ---------------- init: zero counters + dtype detect ----------------
__global__ void k_init(const int* __restrict__ ei32) {
    int i = blockIdx.x * blockDim.x + threadIdx.x;
    if (i < NN) g_cur[i] = 0;
    if (i == 0) {
        int all0 = 1;
        for (int j = 0; j < 64; j++)
            if (ei32[2 * j + 1] != 0) { all0 = 0; break; }
        g_is64 = all0;
    }
}

__device__ __forceinline__ void load_edge(const void* ei, int i, int& s, int& d) {
    if (g_is64) {
        const long long* p = (const long long*)ei;
        s = (int)p[i];
        d = (int)p[NE + i];
    } else {
        const int* p = (const int*)ei;
        s = p[i];
        d = p[NE + i];
    }
}

// ---------------- CSR build ----------------
__global__ void k_hist(const void* __restrict__ ei) {
    int i = blockIdx.x * blockDim.x + threadIdx.x;
    if (i >= NE) return;
    int s, d;
    load_edge(ei, i, s, d);
    atomicAdd(&g_cur[s], 1);
}

__global__ void k_scan1() {
    __shared__ int wsum[8];
    int tid = threadIdx.x;
    int i = blockIdx.x * 256 + tid;
    int lane = tid & 31, warp = tid >> 5;
    int v = (i < NN) ? g_cur[i] : 0;
    int s = v;
    #pragma unroll
    for (int off = 1; off < 32; off <<= 1) {
        int t = __shfl_up_sync(0xffffffffu, s, off);
        if (lane >= off) s += t;
    }
    if (lane == 31) wsum[warp] = s;
    __syncthreads();
    if (tid == 0) {
        int run = 0;
        #pragma unroll
        for (int j = 0; j < 8; j++) { int t = wsum[j]; wsum[j] = run; run += t; }
    }
    __syncthreads();
    int excl = s - v + wsum[warp];
    if (i < NN) g_rowptr[i] = excl;
    if (tid == 255) g_bsum[blockIdx.x] = excl + v;
}

__global__ void k_scan2() {
    __shared__ int wsum[8];
    int tid = threadIdx.x;
    int lane = tid & 31, warp = tid >> 5;
    int v = (tid < NB_SCAN) ? g_bsum[tid] : 0;
    int s = v;
    #pragma unroll
    for (int off = 1; off < 32; off <<= 1) {
        int t = __shfl_up_sync(0xffffffffu, s, off);
        if (lane >= off) s += t;
    }
    if (lane == 31) wsum[warp] = s;
    __syncthreads();
    if (tid == 0) {
        int run = 0;
        #pragma unroll
        for (int j = 0; j < 8; j++) { int t = wsum[j]; wsum[j] = run; run += t; }
    }
    __syncthreads();
    int excl = s - v + wsum[warp];
    if (tid < NB_SCAN) g_bsum[tid] = excl;
    if (tid == 255) g_rowptr[NN] = excl + v;
}

__global__ void k_scan3() {
    int i = blockIdx.x * 256 + threadIdx.x;
    if (i < NN) {
        int r = g_rowptr[i] + g_bsum[blockIdx.x];
        g_rowptr[i] = r;
        g_cur[i] = r;
    }
}

__global__ void k_scatter(const void* __restrict__ ei) {
    int i = blockIdx.x * blockDim.x + threadIdx.x;
    if (i >= NE) return;
    int s, d;
    load_edge(ei, i, s, d);
    int p = atomicAdd(&g_cur[s], 1);
    g_csrdst[p] = d;
}

// =============================================================
// tf32 GEMM kernels. Conflict-free W staging: wT[n][k], k-pad ≡ 4 (mod 32)
// B-frag load addr = bn*PAD + bk; bank = 4*(lane>>2) + (lane&3): all distinct.
// =============================================================

// ---- embedding: x = sc = silu(cat[oh,pos](50000x121, pad 128) @ W + b) ----
__global__ __launch_bounds__(256) void k_emb_t(
    const float* __restrict__ oh, const float* __restrict__ pos,
    const float* __restrict__ W, const float* __restrict__ b)
{
    extern __shared__ unsigned esm[];
    unsigned (*w_hi)[132] = (unsigned (*)[132])esm;            // [64][132]
    unsigned (*w_lo)[132] = (unsigned (*)[132])(esm + 64 * 132);
    int tid = threadIdx.x;
    int lane = tid & 31, warp = tid >> 5;

    for (int idx = tid; idx < 64 * 128; idx += 256) {
        int k = idx >> 6, n = idx & 63;
        float v = (k < 121) ? W[k * 64 + n] : 0.f;
        unsigned hi = f2tf32(v);
        w_hi[n][k] = hi;
        w_lo[n][k] = f2tf32(v - __uint_as_float(hi));
    }
    __syncthreads();

    int m0 = blockIdx.x * 128 + warp * 16;
    int r0 = m0 + (lane >> 2);
    int c0 = lane & 3;

    float acc[8][4];
    #pragma unroll
    for (int i = 0; i < 8; i++)
        #pragma unroll
        for (int j = 0; j < 4; j++) acc[i][j] = 0.f;

    #pragma unroll
    for (int kt = 0; kt < 16; kt++) {
        unsigned ah[4], al[4];
        #pragma unroll
        for (int e = 0; e < 4; e++) {
            int r = min(r0 + (e & 1) * 8, NN - 1);
            int c = kt * 8 + c0 + (e >> 1) * 4;
            float v = 0.f;
            if (c < 118)      v = oh[r * 118 + c];
            else if (c < 121) v = pos[r * 3 + c - 118];
            unsigned hi = f2tf32(v);
            ah[e] = hi;
            al[e] = f2tf32(v - __uint_as_float(hi));
        }
        int bk = kt * 8 + (lane & 3);
        #pragma unroll
        for (int nt = 0; nt < 8; nt++) {
            int bn = nt * 8 + (lane >> 2);
            mma3(acc[nt], ah, al, w_hi[bn][bk], w_hi[bn][bk + 4],
                 w_lo[bn][bk], w_lo[bn][bk + 4]);
        }
    }

    int rA = m0 + (lane >> 2);
    int rB = rA + 8;
    #pragma unroll
    for (int nt = 0; nt < 8; nt++) {
        int col = nt * 8 + 2 * (lane & 3);
        float b0 = b[col], b1 = b[col + 1];
        if (rA < NN) {
            float v0 = fsilu(acc[nt][0] + b0), v1 = fsilu(acc[nt][1] + b1);
            *(float2*)&g_x[rA * 64 + col]  = make_float2(v0, v1);
            *(float2*)&g_sc[rA * 64 + col] = make_float2(v0, v1);
        }
        if (rB < NN) {
            float v0 = fsilu(acc[nt][2] + b0), v1 = fsilu(acc[nt][3] + b1);
            *(float2*)&g_x[rB * 64 + col]  = make_float2(v0, v1);
            *(float2*)&g_sc[rB * 64 + col] = make_float2(v0, v1);
        }
    }
}

// ---- fused interact precompute: A = x @ W[0:64], B = x @ W[64:128] ----
__global__ __launch_bounds__(256) void k_ab(const float* __restrict__ W)
{
    extern __shared__ unsigned absm[];
    unsigned (*w_hi)[132] = (unsigned (*)[132])absm;           // [64][132] (k = 0..127)
    unsigned (*w_lo)[132] = (unsigned (*)[132])(absm + 64 * 132);
    int tid = threadIdx.x;
    int lane = tid & 31, warp = tid >> 5;

    for (int idx = tid; idx < 64 * 128; idx += 256) {
        int k = idx >> 6, n = idx & 63;
        float v = W[k * 64 + n];
        unsigned hi = f2tf32(v);
        w_hi[n][k] = hi;
        w_lo[n][k] = f2tf32(v - __uint_as_float(hi));
    }
    __syncthreads();

    int m0 = blockIdx.x * 128 + warp * 16;
    int r0 = m0 + (lane >> 2);
    int c0 = lane & 3;

    float accA[8][4], accB[8][4];
    #pragma unroll
    for (int i = 0; i < 8; i++)
        #pragma unroll
        for (int j = 0; j < 4; j++) { accA[i][j] = 0.f; accB[i][j] = 0.f; }

    #pragma unroll
    for (int kt = 0; kt < 8; kt++) {
        unsigned ah[4], al[4];
        #pragma unroll
        for (int e = 0; e < 4; e++) {
            int r = min(r0 + (e & 1) * 8, NN - 1);
            int c = kt * 8 + c0 + (e >> 1) * 4;
            float v = g_x[r * 64 + c];
            unsigned hi = f2tf32(v);
            ah[e] = hi;
            al[e] = f2tf32(v - __uint_as_float(hi));
        }
        int bk = kt * 8 + (lane & 3);
        #pragma unroll
        for (int nt = 0; nt < 8; nt++) {
            int bn = nt * 8 + (lane >> 2);
            mma3(accA[nt], ah, al, w_hi[bn][bk], w_hi[bn][bk + 4],
                 w_lo[bn][bk], w_lo[bn][bk + 4]);
            mma3(accB[nt], ah, al, w_hi[bn][64 + bk], w_hi[bn][64 + bk + 4],
                 w_lo[bn][64 + bk], w_lo[bn][64 + bk + 4]);
        }
    }

    int rA = m0 + (lane >> 2);
    int rB = rA + 8;
    #pragma unroll
    for (int nt = 0; nt < 8; nt++) {
        int col = nt * 8 + 2 * (lane & 3);
        if (rA < NN) {
            *(float2*)&g_A[rA * 64 + col] = make_float2(accA[nt][0], accA[nt][1]);
            *(float2*)&g_B[rA * 64 + col] = make_float2(accB[nt][0], accB[nt][1]);
        }
        if (rB < NN) {
            *(float2*)&g_A[rB * 64 + col] = make_float2(accA[nt][2], accA[nt][3]);
            *(float2*)&g_B[rB * 64 + col] = make_float2(accB[nt][2], accB[nt][3]);
        }
    }
}

// ---- update: x += silu(t @ W + b) ----
__global__ __launch_bounds__(256) void k_upd(
    const float* __restrict__ W, const float* __restrict__ bias)
{
    __shared__ unsigned w_hi[64][68];
    __shared__ unsigned w_lo[64][68];
    int tid = threadIdx.x;
    int lane = tid & 31, warp = tid >> 5;

    for (int idx = tid; idx < 4096; idx += 256) {
        int k = idx >> 6, n = idx & 63;
        float v = W[idx];
        unsigned hi = f2tf32(v);
        w_hi[n][k] = hi;
        w_lo[n][k] = f2tf32(v - __uint_as_float(hi));
    }
    __syncthreads();

    int m0 = blockIdx.x * 128 + warp * 16;
    int r0 = m0 + (lane >> 2);
    int c0 = lane & 3;

    float acc[8][4];
    #pragma unroll
    for (int i = 0; i < 8; i++)
        #pragma unroll
        for (int j = 0; j < 4; j++) acc[i][j] = 0.f;

    #pragma unroll
    for (int kt = 0; kt < 8; kt++) {
        unsigned ah[4], al[4];
        #pragma unroll
        for (int e = 0; e < 4; e++) {
            int r = min(r0 + (e & 1) * 8, NN - 1);
            int c = kt * 8 + c0 + (e >> 1) * 4;
            float v = g_t[r * 64 + c];
            unsigned hi = f2tf32(v);
            ah[e] = hi;
            al[e] = f2tf32(v - __uint_as_float(hi));
        }
        int bk = kt * 8 + (lane & 3);
        #pragma unroll
        for (int nt = 0; nt < 8; nt++) {
            int bn = nt * 8 + (lane >> 2);
            mma3(acc[nt], ah, al, w_hi[bn][bk], w_hi[bn][bk + 4],
                 w_lo[bn][bk], w_lo[bn][bk + 4]);
        }
    }

    int rA = m0 + (lane >> 2);
    int rB = rA + 8;
    #pragma unroll
    for (int nt = 0; nt < 8; nt++) {
        int col = nt * 8 + 2 * (lane & 3);
        float b0 = bias[col], b1 = bias[col + 1];
        if (rA < NN) {
            float2 x0 = *(float2*)&g_x[rA * 64 + col];
            x0.x += fsilu(acc[nt][0] + b0);
            x0.y += fsilu(acc[nt][1] + b1);
            *(float2*)&g_x[rA * 64 + col] = x0;
        }
        if (rB < NN) {
            float2 x1 = *(float2*)&g_x[rB * 64 + col];
            x1.x += fsilu(acc[nt][2] + b0);
            x1.y += fsilu(acc[nt][3] + b1);
            *(float2*)&g_x[rB * 64 + col] = x1;
        }
    }
}

// ---------------- edge aggregation ----------------
__global__ __launch_bounds__(256) void k_edge(const float* __restrict__ bias) {
    int gt = blockIdx.x * blockDim.x + threadIdx.x;
    int n = gt >> 5;
    int lane = gt & 31;
    if (n >= NN) return;
    float b0 = bias[lane], b1 = bias[lane + 32];
    float a0 = g_A[n * 64 + lane], a1 = g_A[n * 64 + lane + 32];
    float acc0 = 0.f, acc1 = 0.f;
    int e0 = g_rowptr[n], e1 = g_rowptr[n + 1];
    for (int e = e0; e < e1; e++) {
        int d = g_csrdst[e];
        acc0 += fsilu(a0 + g_B[d * 64 + lane]      + b0);
        acc1 += fsilu(a1 + g_B[d * 64 + lane + 32] + b1);
    }
    g_t[n * 64 + lane]      = g_x[n * 64 + lane]      + 0.25f * acc0;
    g_t[n * 64 + lane + 32] = g_x[n * 64 + lane + 32] + 0.25f * acc1;
}

// ---------------- output ----------------
__global__ __launch_bounds__(256) void k_out(
    const float* __restrict__ Wo, const float* __restrict__ bo, float* __restrict__ out)
{
    int gt = blockIdx.x * blockDim.x + threadIdx.x;
    int n = gt >> 5;
    int lane = gt & 31;
    if (n >= NN) return;
    float v0 = g_sc[n * 64 + lane]      + g_x[n * 64 + lane];
    float v1 = g_sc[n * 64 + lane + 32] + g_x[n * 64 + lane + 32];
    float p0 = v0 * Wo[lane * 3 + 0] + v1 * Wo[(lane + 32) * 3 + 0];
    float p1 = v0 * Wo[lane * 3 + 1] + v1 * Wo[(lane + 32) * 3 + 1];
    float p2 = v0 * Wo[lane * 3 + 2] + v1 * Wo[(lane + 32) * 3 + 2];
    #pragma unroll
    for (int off = 16; off; off >>= 1) {
        p0 += __shfl_down_sync(0xffffffffu, p0, off);
        p1 += __shfl_down_sync(0xffffffffu, p1, off);
        p2 += __shfl_down_sync(0xffffffffu, p2, off);
    }
    if (lane == 0) {
        out[n * 3 + 0] = p0 + bo[0];
        out[n * 3 + 1] = p1 + bo[1];
        out[n * 3 + 2] = p2 + bo[2];
    }
}

// ---------------- launch ----------------
extern "C" void kernel_launch(void* const* d_in, const int* in_sizes, int n_in,
                              void* d_out, int out_size)
{
    const float* oh   = (const float*)d_in[0];
    const float* pos  = (const float*)d_in[1];
    const void*  ei   = d_in[2];
    const float* embW = (const float*)d_in[3];
    const float* embB = (const float*)d_in[4];
    const float* iW   = (const float*)d_in[5];
    const float* iB   = (const float*)d_in[6];
    const float* uW   = (const float*)d_in[7];
    const float* uB   = (const float*)d_in[8];
    const float* oW   = (const float*)d_in[9];
    const float* oB   = (const float*)d_in[10];
    float* out = (float*)d_out;

    const int DSM = 2 * 64 * 132 * 4;   // 67584 bytes
    static int attr_done = 0;
    if (!attr_done) {
        cudaFuncSetAttribute(k_emb_t, cudaFuncAttributeMaxDynamicSharedMemorySize, DSM);
        cudaFuncSetAttribute(k_ab,    cudaFuncAttributeMaxDynamicSharedMemorySize, DSM);
        attr_done = 1;
    }

    k_init<<<(NN + 255) / 256, 256>>>((const int*)ei);
    k_hist<<<(NE + 255) / 256, 256>>>(ei);
    k_scan1<<<NB_SCAN, 256>>>();
    k_scan2<<<1, 256>>>();
    k_scan3<<<NB_SCAN, 256>>>();
    k_scatter<<<(NE + 255) / 256, 256>>>(ei);

    int gb = (NN + 127) / 128;
    k_emb_t<<<gb, 256, DSM>>>(oh, pos, embW, embB);

    for (int l = 0; l < 4; l++) {
        k_ab<<<gb, 256, DSM>>>(iW + l * 8192);
        k_edge<<<(NN * 32) / 256, 256>>>(iB + l * 64);
        k_upd<<<gb, 256>>>(uW + l * 4096, uB + l * 64);
    }

    k_out<<<(NN * 32) / 256, 256>>>(oW, oB, out);
}